// round 6
// baseline (speedup 1.0000x reference)
#include <cuda_runtime.h>
#include <cuda_bf16.h>
#include <cstdint>

// ---------------- problem constants ----------------
#define N_TOK   32768      // B*T
#define DMODEL  1024
#define HDIM    1024
#define NEXP    8
#define TOPK    2
#define NASSIGN (N_TOK * TOPK)       // 65536
#define MAX_TILES 512                // ceil(NASSIGN / 128) worst case per expert

// ---------------- device scratch (no allocation allowed) ----------------
__device__ int   g_expert_id[NASSIGN];
__device__ float g_weight_raw[NASSIGN];
__device__ int   g_counts[NEXP];
__device__ int   g_offsets[NEXP];
__device__ int   g_cursor[NEXP];
__device__ int   g_perm[NASSIGN];     // slot -> token
__device__ float g_wgt[NASSIGN];      // slot -> raw gate score
__device__ float g_h[(size_t)NASSIGN * HDIM];   // 256 MB hidden activations

// ---------------- helpers ----------------
__device__ __forceinline__ uint32_t f2tf32(float x) {
    uint32_t r;
    asm("cvt.rna.tf32.f32 %0, %1;" : "=r"(r) : "f"(x));
    return r;
}

__device__ __forceinline__ void mma_tf32(float c[4], const uint32_t a[4], const uint32_t b[2]) {
    asm volatile(
        "mma.sync.aligned.m16n8k8.row.col.f32.tf32.tf32.f32 "
        "{%0,%1,%2,%3}, {%4,%5,%6,%7}, {%8,%9}, {%0,%1,%2,%3};\n"
        : "+f"(c[0]), "+f"(c[1]), "+f"(c[2]), "+f"(c[3])
        : "r"(a[0]), "r"(a[1]), "r"(a[2]), "r"(a[3]), "r"(b[0]), "r"(b[1]));
}

// ---------------- kernel 0: zero counters ----------------
__global__ void zero_counts_kernel() {
    if (threadIdx.x < NEXP) g_counts[threadIdx.x] = 0;
}

// ---------------- kernel 1: gate (warp per token) ----------------
__global__ void gate_kernel(const float* __restrict__ x,
                            const float* __restrict__ gw,
                            const float* __restrict__ gb) {
    int gwarp = (blockIdx.x * blockDim.x + threadIdx.x) >> 5;
    int lane  = threadIdx.x & 31;
    if (gwarp >= N_TOK) return;
    const float* xr = x + (size_t)gwarp * DMODEL;

    float acc[NEXP];
#pragma unroll
    for (int e = 0; e < NEXP; e++) acc[e] = 0.f;

    for (int d = lane; d < DMODEL; d += 32) {
        float xv = xr[d];
        const float4* g4 = reinterpret_cast<const float4*>(gw + (size_t)d * NEXP);
        float4 ga = g4[0];
        float4 gbv = g4[1];
        acc[0] += xv * ga.x;  acc[1] += xv * ga.y;
        acc[2] += xv * ga.z;  acc[3] += xv * ga.w;
        acc[4] += xv * gbv.x; acc[5] += xv * gbv.y;
        acc[6] += xv * gbv.z; acc[7] += xv * gbv.w;
    }
#pragma unroll
    for (int e = 0; e < NEXP; e++) {
#pragma unroll
        for (int o = 16; o > 0; o >>= 1) acc[e] += __shfl_xor_sync(0xFFFFFFFFu, acc[e], o);
    }

    if (lane == 0) {
        float s[NEXP];
#pragma unroll
        for (int e = 0; e < NEXP; e++) s[e] = acc[e] + gb[e];
        // index-stable top-2 (ties -> lower index, matching lax.top_k)
        int i0 = 0; float b0 = s[0];
#pragma unroll
        for (int e = 1; e < NEXP; e++) if (s[e] > b0) { b0 = s[e]; i0 = e; }
        int i1 = -1; float b1 = -3.4e38f;
#pragma unroll
        for (int e = 0; e < NEXP; e++) if (e != i0 && s[e] > b1) { b1 = s[e]; i1 = e; }

        g_expert_id[2 * gwarp + 0] = i0;
        g_weight_raw[2 * gwarp + 0] = b0;
        g_expert_id[2 * gwarp + 1] = i1;
        g_weight_raw[2 * gwarp + 1] = b1;
        atomicAdd(&g_counts[i0], 1);
        atomicAdd(&g_counts[i1], 1);
    }
}

// ---------------- kernel 2: scan (tiny) ----------------
__global__ void scan_kernel() {
    if (threadIdx.x == 0) {
        int acc = 0;
#pragma unroll
        for (int e = 0; e < NEXP; e++) {
            g_offsets[e] = acc;
            acc += g_counts[e];
            g_cursor[e] = 0;
        }
    }
}

// ---------------- kernel 3: scatter into grouped lists ----------------
__global__ void scatter_kernel() {
    int i = blockIdx.x * blockDim.x + threadIdx.x;
    if (i >= NASSIGN) return;
    int e = g_expert_id[i];
    int pos = g_offsets[e] + atomicAdd(&g_cursor[e], 1);
    g_perm[pos] = i >> 1;
    g_wgt[pos]  = g_weight_raw[i];
}

// ---------------- grouped GEMM: 128x128x1024 tiles, tf32 mma.sync ----------------
// PHASE 1: A = gathered x rows, W = w1, out = g_h with relu(+b1)
// PHASE 2: A = g_h rows (contiguous), W = w2, out = atomicAdd(d_out, s*(acc+b2))
template<int PHASE>
__global__ void __launch_bounds__(256)
moe_gemm_kernel(const float* __restrict__ X,
                const float* __restrict__ W,      // [E, 1024, 1024] k-major rows
                const float* __restrict__ bias,   // [E, 1024]
                float* __restrict__ Out) {
    const int e  = blockIdx.y >> 9;          // / MAX_TILES(512)
    const int mt = blockIdx.y & 511;
    const int cnt = g_counts[e];
    const int m0 = mt * 128;
    if (m0 >= cnt) return;                   // dead tile slot: fast exit
    const int off  = g_offsets[e];
    const int rows = min(128, cnt - m0);
    const int n0 = blockIdx.x * 128;

    __shared__ uint32_t As[128][36];         // padded: conflict-free frag loads
    __shared__ uint32_t Bs[32][132];
    __shared__ const float* sRow[128];
    __shared__ int   sTok[128];
    __shared__ float sW[128];

    const int tid  = threadIdx.x;
    const int lane = tid & 31;
    const int wid  = tid >> 5;
    const int g    = lane >> 2;
    const int tig  = lane & 3;
    const int mBase = (wid & 3) * 32;        // 4 warps over M
    const int nBase = (wid >> 2) * 64;       // 2 warps over N

    if (tid < 128) {
        bool v = tid < rows;
        int slot = off + m0 + tid;
        if (PHASE == 1) {
            sRow[tid] = v ? (X + (size_t)g_perm[slot] * DMODEL) : nullptr;
        } else {
            sRow[tid] = v ? (g_h + (size_t)slot * HDIM) : nullptr;
            sTok[tid] = v ? g_perm[slot] : 0;
            sW[tid]   = v ? g_wgt[slot] : 0.f;
        }
    }
    __syncthreads();

    float acc[2][8][4];
#pragma unroll
    for (int mi = 0; mi < 2; mi++)
#pragma unroll
        for (int ni = 0; ni < 8; ni++)
#pragma unroll
            for (int q = 0; q < 4; q++) acc[mi][ni][q] = 0.f;

    const float* wbase = W + (size_t)e * 1024 * 1024 + n0;

    for (int k0 = 0; k0 < 1024; k0 += 32) {
        // load A tile [128 x 32] (gathered rows), tf32-round into smem
#pragma unroll
        for (int j = 0; j < 4; j++) {
            int id = tid + 256 * j;
            int r = id >> 3, kq = id & 7;
            const float* p = sRow[r];
            float4 v = make_float4(0.f, 0.f, 0.f, 0.f);
            if (p) v = *reinterpret_cast<const float4*>(p + k0 + kq * 4);
            As[r][kq * 4 + 0] = f2tf32(v.x);
            As[r][kq * 4 + 1] = f2tf32(v.y);
            As[r][kq * 4 + 2] = f2tf32(v.z);
            As[r][kq * 4 + 3] = f2tf32(v.w);
        }
        // load B tile [32 x 128]
#pragma unroll
        for (int j = 0; j < 4; j++) {
            int id = tid + 256 * j;
            int kk = id >> 5, nq = id & 31;
            float4 v = *reinterpret_cast<const float4*>(wbase + (size_t)(k0 + kk) * 1024 + nq * 4);
            Bs[kk][nq * 4 + 0] = f2tf32(v.x);
            Bs[kk][nq * 4 + 1] = f2tf32(v.y);
            Bs[kk][nq * 4 + 2] = f2tf32(v.z);
            Bs[kk][nq * 4 + 3] = f2tf32(v.w);
        }
        __syncthreads();

#pragma unroll
        for (int ks = 0; ks < 4; ks++) {
            const int kb = ks * 8;
            uint32_t a[2][4], b[8][2];
#pragma unroll
            for (int mi = 0; mi < 2; mi++) {
                int r = mBase + mi * 16 + g;
                a[mi][0] = As[r][kb + tig];
                a[mi][1] = As[r + 8][kb + tig];
                a[mi][2] = As[r][kb + tig + 4];
                a[mi][3] = As[r + 8][kb + tig + 4];
            }
#pragma unroll
            for (int ni = 0; ni < 8; ni++) {
                int c = nBase + ni * 8 + g;
                b[ni][0] = Bs[kb + tig][c];
                b[ni][1] = Bs[kb + tig + 4][c];
            }
#pragma unroll
            for (int mi = 0; mi < 2; mi++)
#pragma unroll
                for (int ni = 0; ni < 8; ni++)
                    mma_tf32(acc[mi][ni], a[mi], b[ni]);
        }
        __syncthreads();
    }

    // ---------------- epilogue ----------------
#pragma unroll
    for (int mi = 0; mi < 2; mi++) {
        int r0 = mBase + mi * 16 + g;        // rows r0, r0+8
#pragma unroll
        for (int ni = 0; ni < 8; ni++) {
            int ccol = nBase + ni * 8 + 2 * tig;
            float bb0 = __ldg(&bias[e * 1024 + n0 + ccol]);
            float bb1 = __ldg(&bias[e * 1024 + n0 + ccol + 1]);
            if (PHASE == 1) {
                if (r0 < rows) {
                    size_t slot = (size_t)(off + m0 + r0);
                    float v0 = acc[mi][ni][0] + bb0; v0 = v0 > 0.f ? v0 : 0.f;
                    float v1 = acc[mi][ni][1] + bb1; v1 = v1 > 0.f ? v1 : 0.f;
                    *reinterpret_cast<float2*>(&g_h[slot * HDIM + n0 + ccol]) = make_float2(v0, v1);
                }
                if (r0 + 8 < rows) {
                    size_t slot = (size_t)(off + m0 + r0 + 8);
                    float v0 = acc[mi][ni][2] + bb0; v0 = v0 > 0.f ? v0 : 0.f;
                    float v1 = acc[mi][ni][3] + bb1; v1 = v1 > 0.f ? v1 : 0.f;
                    *reinterpret_cast<float2*>(&g_h[slot * HDIM + n0 + ccol]) = make_float2(v0, v1);
                }
            } else {
                if (r0 < rows) {
                    int tok = sTok[r0]; float s = sW[r0];
                    float* op = Out + (size_t)tok * DMODEL + n0 + ccol;
                    atomicAdd(op + 0, s * (acc[mi][ni][0] + bb0));
                    atomicAdd(op + 1, s * (acc[mi][ni][1] + bb1));
                }
                if (r0 + 8 < rows) {
                    int tok = sTok[r0 + 8]; float s = sW[r0 + 8];
                    float* op = Out + (size_t)tok * DMODEL + n0 + ccol;
                    atomicAdd(op + 0, s * (acc[mi][ni][2] + bb0));
                    atomicAdd(op + 1, s * (acc[mi][ni][3] + bb1));
                }
            }
        }
    }
}

// ---------------- launch ----------------
extern "C" void kernel_launch(void* const* d_in, const int* in_sizes, int n_in,
                              void* d_out, int out_size) {
    const float* x  = (const float*)d_in[0];   // [8,4096,1024]
    const float* gw = (const float*)d_in[1];   // [1024,8]
    const float* gb = (const float*)d_in[2];   // [8]
    const float* w1 = (const float*)d_in[3];   // [8,1024,1024]
    const float* b1 = (const float*)d_in[4];   // [8,1024]
    const float* w2 = (const float*)d_in[5];   // [8,1024,1024]
    const float* b2 = (const float*)d_in[6];   // [8,1024]
    float* out = (float*)d_out;

    cudaMemsetAsync(out, 0, (size_t)out_size * sizeof(float), 0);
    zero_counts_kernel<<<1, 32>>>();
    gate_kernel<<<N_TOK / 8, 256>>>(x, gw, gb);         // 8 warps/block -> 8 tokens/block
    scan_kernel<<<1, 32>>>();
    scatter_kernel<<<NASSIGN / 256, 256>>>();

    dim3 gg(HDIM / 128, NEXP * MAX_TILES);              // (8, 4096)
    moe_gemm_kernel<1><<<gg, 256>>>(x, w1, b1, nullptr);
    moe_gemm_kernel<2><<<gg, 256>>>(x, w2, b2, out);
}

// round 10
// speedup vs baseline: 1.6414x; 1.6414x over previous
#include <cuda_runtime.h>
#include <cstdint>

// ---------------- problem constants ----------------
#define N_TOK   32768
#define DMODEL  1024
#define NEXP    8
#define NASSIGN 65536
#define MAX_TILES 512        // worst-case 128-row tiles per expert

// GEMM tile config: BM=128, BN=128, BK=32, 3-stage cp.async pipeline
#define BK      32
#define NKC     (DMODEL / BK)     // 32
#define NSTAGE  3

// shared memory layout (uint32 units for tiles)
#define A_U32   (128 * 36)        // padded stride 36
#define B_U32   (32 * 132)        // padded stride 132
#define STAGE_U (A_U32 + B_U32)   // 8832 u32 = 35328 B
// byte offsets after 3 stages (3*35328 = 105984)
#define SM_ROWB 105984            // 128 row pointers (8B) = 1024B
#define SM_WB   107008            // 128 floats gate weights
#define SM_BIASB 107520           // 128 floats bias tile
#define SM_TOTAL 108032

// ---------------- device scratch (no allocation allowed) ----------------
__device__ int   g_expert_id[NASSIGN];
__device__ float g_weight_raw[NASSIGN];
__device__ int   g_counts[NEXP];
__device__ int   g_offsets[NEXP];
__device__ int   g_cursor[NEXP];
__device__ int   g_perm[NASSIGN];                 // slot -> token
__device__ float g_wgt[NASSIGN];                  // slot -> raw gate score
__device__ int   g_slot[NASSIGN];                 // assignment -> slot
__device__ float g_xr [(size_t)N_TOK * DMODEL];   // tf32-rounded x        (134 MB)
__device__ float g_w1r[(size_t)NEXP * 1024 * 1024]; // tf32-rounded w1     (33 MB)
__device__ float g_w2r[(size_t)NEXP * 1024 * 1024]; // tf32-rounded w2
__device__ float g_h  [(size_t)NASSIGN * DMODEL]; // hidden, tf32-rounded  (268 MB)
__device__ float g_eo [(size_t)NASSIGN * DMODEL]; // weighted expert out   (268 MB)

// ---------------- helpers ----------------
__device__ __forceinline__ uint32_t f2tf32(float x) {
    uint32_t r; asm("cvt.rna.tf32.f32 %0, %1;" : "=r"(r) : "f"(x)); return r;
}
__device__ __forceinline__ uint32_t smem_u32(const void* p) {
    uint32_t a;
    asm("{ .reg .u64 t; cvta.to.shared.u64 t, %1; cvt.u32.u64 %0, t; }" : "=r"(a) : "l"(p));
    return a;
}
__device__ __forceinline__ void cp16(uint32_t dst, const void* src) {
    asm volatile("cp.async.cg.shared.global [%0], [%1], 16;" :: "r"(dst), "l"(src) : "memory");
}
#define CP_COMMIT() asm volatile("cp.async.commit_group;" ::: "memory")
#define CP_WAIT(N)  asm volatile("cp.async.wait_group %0;" :: "n"(N) : "memory")

__device__ __forceinline__ void mma_tf32(float c[4], const uint32_t a[4], const uint32_t b[2]) {
    asm volatile(
        "mma.sync.aligned.m16n8k8.row.col.f32.tf32.tf32.f32 "
        "{%0,%1,%2,%3}, {%4,%5,%6,%7}, {%8,%9}, {%0,%1,%2,%3};\n"
        : "+f"(c[0]), "+f"(c[1]), "+f"(c[2]), "+f"(c[3])
        : "r"(a[0]), "r"(a[1]), "r"(a[2]), "r"(a[3]), "r"(b[0]), "r"(b[1]));
}

// ---------------- kernel: zero counters ----------------
__global__ void zero_counts_kernel() {
    if (threadIdx.x < NEXP) g_counts[threadIdx.x] = 0;
}

// ---------------- kernel: tf32-round copy (x, w1, w2) ----------------
__global__ void round4_kernel(const float4* __restrict__ s, float4* __restrict__ d, int n4) {
    int i = blockIdx.x * blockDim.x + threadIdx.x;
    int stride = gridDim.x * blockDim.x;
    for (; i < n4; i += stride) {
        float4 v = s[i];
        float4 o;
        o.x = __uint_as_float(f2tf32(v.x));
        o.y = __uint_as_float(f2tf32(v.y));
        o.z = __uint_as_float(f2tf32(v.z));
        o.w = __uint_as_float(f2tf32(v.w));
        d[i] = o;
    }
}

// ---------------- kernel: gate (warp per token) ----------------
__global__ void gate_kernel(const float* __restrict__ x,
                            const float* __restrict__ gw,
                            const float* __restrict__ gb) {
    int gwarp = (blockIdx.x * blockDim.x + threadIdx.x) >> 5;
    int lane  = threadIdx.x & 31;
    if (gwarp >= N_TOK) return;
    const float* xr = x + (size_t)gwarp * DMODEL;

    float acc[NEXP];
#pragma unroll
    for (int e = 0; e < NEXP; e++) acc[e] = 0.f;
    for (int d = lane; d < DMODEL; d += 32) {
        float xv = xr[d];
        const float4* g4 = reinterpret_cast<const float4*>(gw + (size_t)d * NEXP);
        float4 ga = g4[0], gbv = g4[1];
        acc[0] += xv * ga.x;  acc[1] += xv * ga.y;
        acc[2] += xv * ga.z;  acc[3] += xv * ga.w;
        acc[4] += xv * gbv.x; acc[5] += xv * gbv.y;
        acc[6] += xv * gbv.z; acc[7] += xv * gbv.w;
    }
#pragma unroll
    for (int e = 0; e < NEXP; e++)
#pragma unroll
        for (int o = 16; o > 0; o >>= 1) acc[e] += __shfl_xor_sync(0xFFFFFFFFu, acc[e], o);

    if (lane == 0) {
        float s[NEXP];
#pragma unroll
        for (int e = 0; e < NEXP; e++) s[e] = acc[e] + gb[e];
        int i0 = 0; float b0 = s[0];
#pragma unroll
        for (int e = 1; e < NEXP; e++) if (s[e] > b0) { b0 = s[e]; i0 = e; }
        int i1 = -1; float b1 = -3.4e38f;
#pragma unroll
        for (int e = 0; e < NEXP; e++) if (e != i0 && s[e] > b1) { b1 = s[e]; i1 = e; }
        g_expert_id[2 * gwarp + 0] = i0;  g_weight_raw[2 * gwarp + 0] = b0;
        g_expert_id[2 * gwarp + 1] = i1;  g_weight_raw[2 * gwarp + 1] = b1;
        atomicAdd(&g_counts[i0], 1);
        atomicAdd(&g_counts[i1], 1);
    }
}

// ---------------- kernel: scan ----------------
__global__ void scan_kernel() {
    if (threadIdx.x == 0) {
        int acc = 0;
#pragma unroll
        for (int e = 0; e < NEXP; e++) { g_offsets[e] = acc; acc += g_counts[e]; g_cursor[e] = 0; }
    }
}

// ---------------- kernel: scatter ----------------
__global__ void scatter_kernel() {
    int i = blockIdx.x * blockDim.x + threadIdx.x;
    if (i >= NASSIGN) return;
    int e = g_expert_id[i];
    int pos = g_offsets[e] + atomicAdd(&g_cursor[e], 1);
    g_perm[pos] = i >> 1;
    g_wgt[pos]  = g_weight_raw[i];
    g_slot[i]   = pos;
}

// ---------------- grouped GEMM: 128x128x1024, tf32 mma.sync, 3-stage cp.async ----------------
// PHASE 1: A = gathered g_xr rows, W = g_w1r, out = g_h = tf32(relu(acc+b1))
// PHASE 2: A = g_h rows (contiguous, pre-rounded), W = g_w2r, out = g_eo = s*(acc+b2)
template<int PHASE>
__global__ void __launch_bounds__(256)
moe_gemm(const float* __restrict__ bias) {
    const int e  = blockIdx.y >> 9;
    const int mt = blockIdx.y & 511;
    const int cnt = g_counts[e];
    const int m0 = mt * 128;
    if (m0 >= cnt) return;
    const int off  = g_offsets[e];
    const int rows = min(128, cnt - m0);
    const int n0 = blockIdx.x * 128;

    extern __shared__ char smem[];
    uint32_t* smu = (uint32_t*)smem;
    const uint32_t su = smem_u32(smem);
    const int tid = threadIdx.x, lane = tid & 31, wid = tid >> 5;

    const float* W = (PHASE == 1) ? g_w1r : g_w2r;
    const float* wbase = W + ((size_t)e << 20) + n0;   // element (k,n): wbase + k*1024 + (n-n0)

    const float** sRow = (const float**)(smem + SM_ROWB);
    float* sW    = (float*)(smem + SM_WB);
    float* sBias = (float*)(smem + SM_BIASB);

    if (tid < 128) {
        int rr = min(tid, rows - 1);               // clamp: garbage rows computed, never stored
        int slot = off + m0 + rr;
        sRow[tid] = (PHASE == 1) ? (g_xr + (size_t)g_perm[slot] * DMODEL)
                                 : (g_h + (size_t)slot * DMODEL);
        if (PHASE == 2) sW[tid] = (tid < rows) ? g_wgt[off + m0 + tid] : 0.f;
        sBias[tid] = bias[e * 1024 + n0 + tid];
    }
    __syncthreads();

    // per-thread cp.async plan: 4 A segments + 4 B segments of 16B per stage
    const float* aSrc[4];
    const float* bSrc[4];
    uint32_t dA[4], dB[4];
#pragma unroll
    for (int j = 0; j < 4; j++) {
        int id = tid + 256 * j;
        int r = id >> 3, seg = id & 7;             // A: 128 rows x 8 segs
        aSrc[j] = sRow[r] + seg * 4;
        dA[j] = su + (uint32_t)(r * 36 + seg * 4) * 4;
        int kk = id >> 5, nseg = id & 31;          // B: 32 k-rows x 32 segs
        bSrc[j] = wbase + (size_t)kk * 1024 + nseg * 4;
        dB[j] = su + (uint32_t)(A_U32 + kk * 132 + nseg * 4) * 4;
    }

    auto load_stage = [&](int kc, int buf) {
        const uint32_t sb = (uint32_t)(buf * STAGE_U) * 4;
        const int k0 = kc * BK;
#pragma unroll
        for (int j = 0; j < 4; j++) cp16(dA[j] + sb, aSrc[j] + k0);
#pragma unroll
        for (int j = 0; j < 4; j++) cp16(dB[j] + sb, bSrc[j] + (size_t)k0 * 1024);
        CP_COMMIT();
    };

    load_stage(0, 0);
    load_stage(1, 1);

    float acc[2][8][4];
#pragma unroll
    for (int mi = 0; mi < 2; mi++)
#pragma unroll
        for (int ni = 0; ni < 8; ni++)
#pragma unroll
            for (int q = 0; q < 4; q++) acc[mi][ni][q] = 0.f;

    const int g   = lane >> 2;
    const int tig = lane & 3;
    const int mBase = (wid & 3) * 32;              // 4 warps over M
    const int nBase = (wid >> 2) * 64;             // 2 warps over N

    for (int kc = 0; kc < NKC; kc++) {
        if (kc + 1 < NKC) { CP_WAIT(1); } else { CP_WAIT(0); }
        __syncthreads();                           // stage kc visible; prev compute done
        if (kc + 2 < NKC) load_stage(kc + 2, (kc + 2) % NSTAGE);

        const uint32_t* As = smu + (kc % NSTAGE) * STAGE_U;
        const uint32_t* Bs = As + A_U32;

#pragma unroll
        for (int ks = 0; ks < 4; ks++) {
            const int kb = ks * 8;
            uint32_t a[2][4], b[8][2];
#pragma unroll
            for (int mi = 0; mi < 2; mi++) {
                int r = mBase + mi * 16 + g;
                a[mi][0] = As[r * 36 + kb + tig];
                a[mi][1] = As[(r + 8) * 36 + kb + tig];
                a[mi][2] = As[r * 36 + kb + tig + 4];
                a[mi][3] = As[(r + 8) * 36 + kb + tig + 4];
            }
#pragma unroll
            for (int ni = 0; ni < 8; ni++) {
                int c = nBase + ni * 8 + g;
                b[ni][0] = Bs[(kb + tig) * 132 + c];
                b[ni][1] = Bs[(kb + tig + 4) * 132 + c];
            }
#pragma unroll
            for (int mi = 0; mi < 2; mi++)
#pragma unroll
                for (int ni = 0; ni < 8; ni++)
                    mma_tf32(acc[mi][ni], a[mi], b[ni]);
        }
    }

    // ---------------- epilogue (no atomics) ----------------
#pragma unroll
    for (int mi = 0; mi < 2; mi++) {
        int r0 = mBase + mi * 16 + g;
#pragma unroll
        for (int ni = 0; ni < 8; ni++) {
            int ccol = nBase + ni * 8 + 2 * tig;
            float bb0 = sBias[ccol], bb1 = sBias[ccol + 1];
            if (r0 < rows) {
                size_t slot = (size_t)(off + m0 + r0);
                if (PHASE == 1) {
                    float v0 = acc[mi][ni][0] + bb0; v0 = v0 > 0.f ? v0 : 0.f;
                    float v1 = acc[mi][ni][1] + bb1; v1 = v1 > 0.f ? v1 : 0.f;
                    *(float2*)&g_h[slot * DMODEL + n0 + ccol] =
                        make_float2(__uint_as_float(f2tf32(v0)), __uint_as_float(f2tf32(v1)));
                } else {
                    float s = sW[r0];
                    *(float2*)&g_eo[slot * DMODEL + n0 + ccol] =
                        make_float2(s * (acc[mi][ni][0] + bb0), s * (acc[mi][ni][1] + bb1));
                }
            }
            if (r0 + 8 < rows) {
                size_t slot = (size_t)(off + m0 + r0 + 8);
                if (PHASE == 1) {
                    float v0 = acc[mi][ni][2] + bb0; v0 = v0 > 0.f ? v0 : 0.f;
                    float v1 = acc[mi][ni][3] + bb1; v1 = v1 > 0.f ? v1 : 0.f;
                    *(float2*)&g_h[slot * DMODEL + n0 + ccol] =
                        make_float2(__uint_as_float(f2tf32(v0)), __uint_as_float(f2tf32(v1)));
                } else {
                    float s = sW[r0 + 8];
                    *(float2*)&g_eo[slot * DMODEL + n0 + ccol] =
                        make_float2(s * (acc[mi][ni][2] + bb0), s * (acc[mi][ni][3] + bb1));
                }
            }
        }
    }
}

// ---------------- kernel: combine (deterministic, no atomics) ----------------
__global__ void combine_kernel(float* __restrict__ out) {
    const int t = blockIdx.x;
    const int s0 = g_slot[2 * t], s1 = g_slot[2 * t + 1];
    const float4* a = (const float4*)(g_eo + (size_t)s0 * DMODEL);
    const float4* b = (const float4*)(g_eo + (size_t)s1 * DMODEL);
    float4* o = (float4*)(out + (size_t)t * DMODEL);
    const int i = threadIdx.x;          // 256 threads x float4 = 1024 floats
    float4 va = a[i], vb = b[i];
    o[i] = make_float4(va.x + vb.x, va.y + vb.y, va.z + vb.z, va.w + vb.w);
}

// ---------------- launch ----------------
extern "C" void kernel_launch(void* const* d_in, const int* in_sizes, int n_in,
                              void* d_out, int out_size) {
    const float* x  = (const float*)d_in[0];
    const float* gw = (const float*)d_in[1];
    const float* gb = (const float*)d_in[2];
    const float* w1 = (const float*)d_in[3];
    const float* b1 = (const float*)d_in[4];
    const float* w2 = (const float*)d_in[5];
    const float* b2 = (const float*)d_in[6];
    float* out = (float*)d_out;

    cudaFuncSetAttribute(moe_gemm<1>, cudaFuncAttributeMaxDynamicSharedMemorySize, SM_TOTAL);
    cudaFuncSetAttribute(moe_gemm<2>, cudaFuncAttributeMaxDynamicSharedMemorySize, SM_TOTAL);

    zero_counts_kernel<<<1, 32>>>();

    // tf32-round inputs/weights once (pure bandwidth)
    float* xr  = nullptr; cudaGetSymbolAddress((void**)&xr,  g_xr);
    float* w1r = nullptr; cudaGetSymbolAddress((void**)&w1r, g_w1r);
    float* w2r = nullptr; cudaGetSymbolAddress((void**)&w2r, g_w2r);
    round4_kernel<<<4096, 256>>>((const float4*)x,  (float4*)xr,  N_TOK * DMODEL / 4);
    round4_kernel<<<2048, 256>>>((const float4*)w1, (float4*)w1r, NEXP * 1024 * 1024 / 4);
    round4_kernel<<<2048, 256>>>((const float4*)w2, (float4*)w2r, NEXP * 1024 * 1024 / 4);

    gate_kernel<<<N_TOK / 8, 256>>>(x, gw, gb);
    scan_kernel<<<1, 32>>>();
    scatter_kernel<<<NASSIGN / 256, 256>>>();

    dim3 gg(DMODEL / 128, NEXP * MAX_TILES);   // (8, 4096)
    moe_gemm<1><<<gg, 256, SM_TOTAL>>>(b1);
    moe_gemm<2><<<gg, 256, SM_TOTAL>>>(b2);

    combine_kernel<<<N_TOK, 256>>>(out);
}

// round 13
// speedup vs baseline: 2.7562x; 1.6792x over previous
#include <cuda_runtime.h>
#include <cuda_fp16.h>
#include <cstdint>

// ---------------- problem constants ----------------
#define N_TOK   32768
#define DMODEL  1024
#define NEXP    8
#define NASSIGN 65536
#define MAX_TILES 512        // worst-case 128-row tiles per expert

// GEMM tile: BM=128, BN=128, BK=32 (halves), 3-stage cp.async, fp16 HMMA
#define BK      32
#define NKC     (DMODEL / BK)     // 32
#define NSTAGE  3

// smem layout (bytes). Tile rows padded to 40 halves (80B): bank = 20*g + tig
// over a warp's fragment loads -> full 32-lane permutation, conflict-free.
#define ROW_B   80                // bytes per padded row (40 halves)
#define ROW_U   20                // u32 per padded row
#define A_HB    (128 * ROW_B)     // 10240 B
#define STAGE_B (2 * A_HB)        // 20480 B (A + B)
#define SM_ROWB (NSTAGE * STAGE_B)        // 61440: 128 row pointers (8B)
#define SM_WB   (SM_ROWB + 1024)          // 62464: 128 floats gate weights
#define SM_BIASB (SM_WB + 512)            // 62976: 128 floats bias tile
#define SM_TOTAL (SM_BIASB + 512)         // 63488

// ---------------- device scratch (no allocation allowed) ----------------
__device__ int    g_expert_id[NASSIGN];
__device__ float  g_weight_raw[NASSIGN];
__device__ int    g_counts[NEXP];
__device__ int    g_offsets[NEXP];
__device__ int    g_cursor[NEXP];
__device__ int    g_perm[NASSIGN];                 // slot -> token
__device__ float  g_wgt[NASSIGN];                  // slot -> raw gate score
__device__ int    g_slot[NASSIGN];                 // assignment -> slot
__device__ __half g_xh [(size_t)N_TOK * DMODEL];       // x in fp16         (67 MB)
__device__ __half g_w1h[(size_t)NEXP * 1024 * 1024];   // w1^T [e][n][k]    (17 MB)
__device__ __half g_w2h[(size_t)NEXP * 1024 * 1024];   // w2^T [e][n][k]
__device__ __half g_h  [(size_t)NASSIGN * DMODEL];     // hidden fp16       (134 MB)
__device__ float  g_eo [(size_t)NASSIGN * DMODEL];     // weighted out f32  (268 MB)

// ---------------- helpers ----------------
__device__ __forceinline__ uint32_t smem_u32(const void* p) {
    uint32_t a;
    asm("{ .reg .u64 t; cvta.to.shared.u64 t, %1; cvt.u32.u64 %0, t; }" : "=r"(a) : "l"(p));
    return a;
}
__device__ __forceinline__ void cp16(uint32_t dst, const void* src) {
    asm volatile("cp.async.cg.shared.global [%0], [%1], 16;" :: "r"(dst), "l"(src) : "memory");
}
#define CP_COMMIT() asm volatile("cp.async.commit_group;" ::: "memory")
#define CP_WAIT(N)  asm volatile("cp.async.wait_group %0;" :: "n"(N) : "memory")

__device__ __forceinline__ void mma_f16(float c[4], const uint32_t a[4], const uint32_t b[2]) {
    asm volatile(
        "mma.sync.aligned.m16n8k16.row.col.f32.f16.f16.f32 "
        "{%0,%1,%2,%3}, {%4,%5,%6,%7}, {%8,%9}, {%0,%1,%2,%3};\n"
        : "+f"(c[0]), "+f"(c[1]), "+f"(c[2]), "+f"(c[3])
        : "r"(a[0]), "r"(a[1]), "r"(a[2]), "r"(a[3]), "r"(b[0]), "r"(b[1]));
}

// ---------------- kernel: zero counters ----------------
__global__ void zero_counts_kernel() {
    if (threadIdx.x < NEXP) g_counts[threadIdx.x] = 0;
}

// ---------------- kernel: x -> fp16 ----------------
__global__ void cvt_x_kernel(const float4* __restrict__ s, __half2* __restrict__ d, int n4) {
    int i = blockIdx.x * blockDim.x + threadIdx.x;
    int stride = gridDim.x * blockDim.x;
    for (; i < n4; i += stride) {
        float4 v = s[i];
        d[2 * i + 0] = __floats2half2_rn(v.x, v.y);
        d[2 * i + 1] = __floats2half2_rn(v.z, v.w);
    }
}

// ---------------- kernel: weights -> transposed fp16 [e][n][k] ----------------
template<int WHICH>
__global__ void transpose_h_kernel(const float* __restrict__ src) {
    __shared__ float tile[32][33];
    __half* dst = (WHICH == 1) ? g_w1h : g_w2h;
    int e = blockIdx.z;
    int kb = blockIdx.y * 32, nb = blockIdx.x * 32;
    const float* s = src + ((size_t)e << 20);
    __half* d = dst + ((size_t)e << 20);
    int tx = threadIdx.x, ty = threadIdx.y;
#pragma unroll
    for (int i = 0; i < 32; i += 8)
        tile[ty + i][tx] = s[(size_t)(kb + ty + i) * 1024 + nb + tx];
    __syncthreads();
#pragma unroll
    for (int i = 0; i < 32; i += 8)
        d[(size_t)(nb + ty + i) * 1024 + kb + tx] = __float2half_rn(tile[tx][ty + i]);
}

// ---------------- kernel: gate (warp per token, fp32) ----------------
__global__ void gate_kernel(const float* __restrict__ x,
                            const float* __restrict__ gw,
                            const float* __restrict__ gb) {
    int gwarp = (blockIdx.x * blockDim.x + threadIdx.x) >> 5;
    int lane  = threadIdx.x & 31;
    if (gwarp >= N_TOK) return;
    const float* xr = x + (size_t)gwarp * DMODEL;

    float acc[NEXP];
#pragma unroll
    for (int e = 0; e < NEXP; e++) acc[e] = 0.f;
    for (int d = lane; d < DMODEL; d += 32) {
        float xv = xr[d];
        const float4* g4 = reinterpret_cast<const float4*>(gw + (size_t)d * NEXP);
        float4 ga = g4[0], gbv = g4[1];
        acc[0] += xv * ga.x;  acc[1] += xv * ga.y;
        acc[2] += xv * ga.z;  acc[3] += xv * ga.w;
        acc[4] += xv * gbv.x; acc[5] += xv * gbv.y;
        acc[6] += xv * gbv.z; acc[7] += xv * gbv.w;
    }
#pragma unroll
    for (int e = 0; e < NEXP; e++)
#pragma unroll
        for (int o = 16; o > 0; o >>= 1) acc[e] += __shfl_xor_sync(0xFFFFFFFFu, acc[e], o);

    if (lane == 0) {
        float s[NEXP];
#pragma unroll
        for (int e = 0; e < NEXP; e++) s[e] = acc[e] + gb[e];
        int i0 = 0; float b0 = s[0];
#pragma unroll
        for (int e = 1; e < NEXP; e++) if (s[e] > b0) { b0 = s[e]; i0 = e; }
        int i1 = -1; float b1 = -3.4e38f;
#pragma unroll
        for (int e = 0; e < NEXP; e++) if (e != i0 && s[e] > b1) { b1 = s[e]; i1 = e; }
        g_expert_id[2 * gwarp + 0] = i0;  g_weight_raw[2 * gwarp + 0] = b0;
        g_expert_id[2 * gwarp + 1] = i1;  g_weight_raw[2 * gwarp + 1] = b1;
        atomicAdd(&g_counts[i0], 1);
        atomicAdd(&g_counts[i1], 1);
    }
}

// ---------------- kernel: scan ----------------
__global__ void scan_kernel() {
    if (threadIdx.x == 0) {
        int acc = 0;
#pragma unroll
        for (int e = 0; e < NEXP; e++) { g_offsets[e] = acc; acc += g_counts[e]; g_cursor[e] = 0; }
    }
}

// ---------------- kernel: scatter ----------------
__global__ void scatter_kernel() {
    int i = blockIdx.x * blockDim.x + threadIdx.x;
    if (i >= NASSIGN) return;
    int e = g_expert_id[i];
    int pos = g_offsets[e] + atomicAdd(&g_cursor[e], 1);
    g_perm[pos] = i >> 1;
    g_wgt[pos]  = g_weight_raw[i];
    g_slot[i]   = pos;
}

// ---------------- grouped GEMM: 128x128x1024 fp16 HMMA, 3-stage cp.async ----------------
// A smem [m][k], B smem [n][k] (both k-contiguous), padded row = 40 halves.
// PHASE 1: A = gathered g_xh rows, B = g_w1h, out = g_h = half(relu(acc+b1))
// PHASE 2: A = g_h rows (contiguous),  B = g_w2h, out = g_eo = s*(acc+b2)  (fp32)
template<int PHASE>
__global__ void __launch_bounds__(256)
moe_gemm(const float* __restrict__ bias) {
    const int e  = blockIdx.y >> 9;
    const int mt = blockIdx.y & 511;
    const int cnt = g_counts[e];
    const int m0 = mt * 128;
    if (m0 >= cnt) return;
    const int off  = g_offsets[e];
    const int rows = min(128, cnt - m0);
    const int n0 = blockIdx.x * 128;

    extern __shared__ char smem[];
    const uint32_t su = smem_u32(smem);
    const int tid = threadIdx.x, lane = tid & 31, wid = tid >> 5;

    const __half* Wh = ((PHASE == 1) ? g_w1h : g_w2h) + ((size_t)e << 20) + (size_t)n0 * 1024;

    const __half** sRow = (const __half**)(smem + SM_ROWB);
    float* sW    = (float*)(smem + SM_WB);
    float* sBias = (float*)(smem + SM_BIASB);

    if (tid < 128) {
        int rr = min(tid, rows - 1);               // clamp: garbage computed, never stored
        int slot = off + m0 + rr;
        sRow[tid] = (PHASE == 1) ? (g_xh + (size_t)g_perm[slot] * DMODEL)
                                 : (g_h + (size_t)slot * DMODEL);
        if (PHASE == 2) sW[tid] = (tid < rows) ? g_wgt[off + m0 + tid] : 0.f;
        sBias[tid] = bias[e * 1024 + n0 + tid];
    }
    __syncthreads();

    // per-thread cp.async plan: 2 A + 2 B segments of 16B (8 halves) per stage
    const __half* aSrc[2];
    const __half* bSrc[2];
    uint32_t dA[2], dB[2];
#pragma unroll
    for (int j = 0; j < 2; j++) {
        int id = tid + 256 * j;
        int r = id >> 2, seg = id & 3;             // 128 rows x 4 segs (32 halves/row)
        aSrc[j] = sRow[r] + seg * 8;
        dA[j] = su + (uint32_t)(r * ROW_B + seg * 16);
        bSrc[j] = Wh + (size_t)r * 1024 + seg * 8; // B row = output col n
        dB[j] = su + (uint32_t)(A_HB + r * ROW_B + seg * 16);
    }

    auto load_stage = [&](int kc, int buf) {
        const uint32_t sb = (uint32_t)(buf * STAGE_B);
        const int k0 = kc * BK;
#pragma unroll
        for (int j = 0; j < 2; j++) cp16(dA[j] + sb, aSrc[j] + k0);
#pragma unroll
        for (int j = 0; j < 2; j++) cp16(dB[j] + sb, bSrc[j] + k0);
        CP_COMMIT();
    };

    load_stage(0, 0);
    load_stage(1, 1);

    float acc[2][8][4];
#pragma unroll
    for (int mi = 0; mi < 2; mi++)
#pragma unroll
        for (int ni = 0; ni < 8; ni++)
#pragma unroll
            for (int q = 0; q < 4; q++) acc[mi][ni][q] = 0.f;

    const int g   = lane >> 2;
    const int tig = lane & 3;
    const int mBase = (wid & 3) * 32;              // 4 warps over M
    const int nBase = (wid >> 2) * 64;             // 2 warps over N

    for (int kc = 0; kc < NKC; kc++) {
        if (kc + 1 < NKC) { CP_WAIT(1); } else { CP_WAIT(0); }
        __syncthreads();
        if (kc + 2 < NKC) load_stage(kc + 2, (kc + 2) % NSTAGE);

        const uint32_t* Au = (const uint32_t*)(smem + (kc % NSTAGE) * STAGE_B);
        const uint32_t* Bu = Au + A_HB / 4;

#pragma unroll
        for (int ks = 0; ks < 2; ks++) {
            const int kb = ks * 8;                 // u32 offset of k-block
            uint32_t a[2][4], b[8][2];
#pragma unroll
            for (int mi = 0; mi < 2; mi++) {
                int r = mBase + mi * 16 + g;
                a[mi][0] = Au[r * ROW_U + kb + tig];
                a[mi][1] = Au[(r + 8) * ROW_U + kb + tig];
                a[mi][2] = Au[r * ROW_U + kb + tig + 4];
                a[mi][3] = Au[(r + 8) * ROW_U + kb + tig + 4];
            }
#pragma unroll
            for (int ni = 0; ni < 8; ni++) {
                int c = nBase + ni * 8 + g;
                b[ni][0] = Bu[c * ROW_U + kb + tig];
                b[ni][1] = Bu[c * ROW_U + kb + tig + 4];
            }
#pragma unroll
            for (int mi = 0; mi < 2; mi++)
#pragma unroll
                for (int ni = 0; ni < 8; ni++)
                    mma_f16(acc[mi][ni], a[mi], b[ni]);
        }
    }

    // ---------------- epilogue (no atomics) ----------------
#pragma unroll
    for (int mi = 0; mi < 2; mi++) {
        int r0 = mBase + mi * 16 + g;
#pragma unroll
        for (int ni = 0; ni < 8; ni++) {
            int ccol = nBase + ni * 8 + 2 * tig;
            float bb0 = sBias[ccol], bb1 = sBias[ccol + 1];
            if (r0 < rows) {
                size_t slot = (size_t)(off + m0 + r0);
                if (PHASE == 1) {
                    float v0 = acc[mi][ni][0] + bb0; v0 = v0 > 0.f ? v0 : 0.f;
                    float v1 = acc[mi][ni][1] + bb1; v1 = v1 > 0.f ? v1 : 0.f;
                    *(__half2*)&g_h[slot * DMODEL + n0 + ccol] = __floats2half2_rn(v0, v1);
                } else {
                    float s = sW[r0];
                    *(float2*)&g_eo[slot * DMODEL + n0 + ccol] =
                        make_float2(s * (acc[mi][ni][0] + bb0), s * (acc[mi][ni][1] + bb1));
                }
            }
            if (r0 + 8 < rows) {
                size_t slot = (size_t)(off + m0 + r0 + 8);
                if (PHASE == 1) {
                    float v0 = acc[mi][ni][2] + bb0; v0 = v0 > 0.f ? v0 : 0.f;
                    float v1 = acc[mi][ni][3] + bb1; v1 = v1 > 0.f ? v1 : 0.f;
                    *(__half2*)&g_h[slot * DMODEL + n0 + ccol] = __floats2half2_rn(v0, v1);
                } else {
                    float s = sW[r0 + 8];
                    *(float2*)&g_eo[slot * DMODEL + n0 + ccol] =
                        make_float2(s * (acc[mi][ni][2] + bb0), s * (acc[mi][ni][3] + bb1));
                }
            }
        }
    }
}

// ---------------- kernel: combine (deterministic, no atomics) ----------------
__global__ void combine_kernel(float* __restrict__ out) {
    const int t = blockIdx.x;
    const int s0 = g_slot[2 * t], s1 = g_slot[2 * t + 1];
    const float4* a = (const float4*)(g_eo + (size_t)s0 * DMODEL);
    const float4* b = (const float4*)(g_eo + (size_t)s1 * DMODEL);
    float4* o = (float4*)(out + (size_t)t * DMODEL);
    const int i = threadIdx.x;          // 256 threads x float4 = 1024 floats
    float4 va = a[i], vb = b[i];
    o[i] = make_float4(va.x + vb.x, va.y + vb.y, va.z + vb.z, va.w + vb.w);
}

// ---------------- launch ----------------
extern "C" void kernel_launch(void* const* d_in, const int* in_sizes, int n_in,
                              void* d_out, int out_size) {
    const float* x  = (const float*)d_in[0];
    const float* gw = (const float*)d_in[1];
    const float* gb = (const float*)d_in[2];
    const float* w1 = (const float*)d_in[3];
    const float* b1 = (const float*)d_in[4];
    const float* w2 = (const float*)d_in[5];
    const float* b2 = (const float*)d_in[6];
    float* out = (float*)d_out;

    cudaFuncSetAttribute(moe_gemm<1>, cudaFuncAttributeMaxDynamicSharedMemorySize, SM_TOTAL);
    cudaFuncSetAttribute(moe_gemm<2>, cudaFuncAttributeMaxDynamicSharedMemorySize, SM_TOTAL);

    zero_counts_kernel<<<1, 32>>>();

    // fp16 conversion pre-pass
    __half* xh = nullptr; cudaGetSymbolAddress((void**)&xh, g_xh);
    cvt_x_kernel<<<4096, 256>>>((const float4*)x, (__half2*)xh, N_TOK * DMODEL / 4);
    {
        dim3 tb(32, 8), tg(32, 32, NEXP);
        transpose_h_kernel<1><<<tg, tb>>>(w1);
        transpose_h_kernel<2><<<tg, tb>>>(w2);
    }

    gate_kernel<<<N_TOK / 8, 256>>>(x, gw, gb);
    scan_kernel<<<1, 32>>>();
    scatter_kernel<<<NASSIGN / 256, 256>>>();

    dim3 gg(DMODEL / 128, NEXP * MAX_TILES);   // (8, 4096)
    moe_gemm<1><<<gg, 256, SM_TOTAL>>>(b1);
    moe_gemm<2><<<gg, 256, SM_TOTAL>>>(b2);

    combine_kernel<<<N_TOK, 256>>>(out);
}